// round 3
// baseline (speedup 1.0000x reference)
#include <cuda_runtime.h>

#define H        1024
#define S        32768
#define THREADS  256
#define WARPS    (THREADS / 32)
#define GRID     296                         // 148 SMs * 2 CTAs: one balanced wave
#define N_WARPS  (GRID * WARPS)              // 2368
#define ROWS_PW  ((S + N_WARPS - 1) / N_WARPS)   // 14 contiguous rows per warp
#define VEC      8                           // 8 x float4 per thread = 32 cols

__global__ void zero_out_kernel(float* __restrict__ out) {
    int i = blockIdx.x * blockDim.x + threadIdx.x;
    if (i < H) out[i] = 0.0f;
}

__device__ __forceinline__ void load_row(float4 (&kv)[VEC],
                                         const float* __restrict__ keys,
                                         int row, int lane) {
    const float4* kr = reinterpret_cast<const float4*>(keys + (size_t)row * H);
#pragma unroll
    for (int j = 0; j < VEC; j++)
        kv[j] = __ldcs(&kr[j * 32 + lane]);
}

__device__ __forceinline__ void process_row(const float4 (&kv)[VEC],
                                            const float4* __restrict__ s_q4,
                                            float inv_qn, int lane,
                                            float (&acc)[VEC * 4]) {
    float dot = 0.0f, kss = 0.0f;
#pragma unroll
    for (int j = 0; j < VEC; j++) {
        float4 q = s_q4[j * 32 + lane];
        dot += q.x * kv[j].x + q.y * kv[j].y + q.z * kv[j].z + q.w * kv[j].w;
        kss += kv[j].x * kv[j].x + kv[j].y * kv[j].y
             + kv[j].z * kv[j].z + kv[j].w * kv[j].w;
    }
#pragma unroll
    for (int o = 16; o > 0; o >>= 1) {
        dot += __shfl_xor_sync(0xFFFFFFFFu, dot, o);
        kss += __shfl_xor_sync(0xFFFFFFFFu, kss, o);
    }
    const float score = dot * inv_qn * rsqrtf(kss);
#pragma unroll
    for (int j = 0; j < VEC; j++) {
        acc[j * 4 + 0] += score * kv[j].x;
        acc[j * 4 + 1] += score * kv[j].y;
        acc[j * 4 + 2] += score * kv[j].z;
        acc[j * 4 + 3] += score * kv[j].w;
    }
}

__global__ __launch_bounds__(THREADS, 2)
void bahdanau_cos_kernel(const float* __restrict__ query,
                         const float* __restrict__ keys,
                         float* __restrict__ out) {
    __shared__ float s_q[H];
    __shared__ float s_ctx[H];

    const int tid  = threadIdx.x;
    const int lane = tid & 31;
    const int warp = tid >> 5;

    for (int i = tid; i < H; i += THREADS) {
        s_q[i]   = query[i];
        s_ctx[i] = 0.0f;
    }
    __syncthreads();

    const float4* s_q4 = reinterpret_cast<const float4*>(s_q);

    // every warp independently computes ||q||^-1 from smem (cheap, no extra sync)
    float qss = 0.0f;
#pragma unroll
    for (int j = 0; j < VEC; j++) {
        float4 q = s_q4[j * 32 + lane];
        qss += q.x * q.x + q.y * q.y + q.z * q.z + q.w * q.w;
    }
#pragma unroll
    for (int o = 16; o > 0; o >>= 1)
        qss += __shfl_xor_sync(0xFFFFFFFFu, qss, o);
    const float inv_qn = rsqrtf(qss);

    float acc[VEC * 4];
#pragma unroll
    for (int i = 0; i < VEC * 4; i++) acc[i] = 0.0f;

    // contiguous chunk of rows for this warp
    const int gw    = blockIdx.x * WARPS + warp;
    const int start = gw * ROWS_PW;
    const int end   = min(start + ROWS_PW, S);

    // software-pipelined: next row's loads are in flight during the
    // shuffle-reduce / score / accumulate of the current row.
    if (start < end) {
        float4 bufA[VEC], bufB[VEC];
        int row = start;
        load_row(bufA, keys, row, lane);
        while (true) {
            int r2 = row + 1;
            bool v2 = r2 < end;
            if (v2) load_row(bufB, keys, r2, lane);
            process_row(bufA, s_q4, inv_qn, lane, acc);
            if (!v2) break;

            int r3 = r2 + 1;
            bool v3 = r3 < end;
            if (v3) load_row(bufA, keys, r3, lane);
            process_row(bufB, s_q4, inv_qn, lane, acc);
            if (!v3) break;
            row = r3;
        }
    }

    __syncthreads();   // s_ctx zero visible to all

    // warp partials -> shared context
#pragma unroll
    for (int j = 0; j < VEC; j++) {
        const int col = j * 128 + lane * 4;
        atomicAdd(&s_ctx[col + 0], acc[j * 4 + 0]);
        atomicAdd(&s_ctx[col + 1], acc[j * 4 + 1]);
        atomicAdd(&s_ctx[col + 2], acc[j * 4 + 2]);
        atomicAdd(&s_ctx[col + 3], acc[j * 4 + 3]);
    }
    __syncthreads();

    // block partial -> global output
    for (int i = tid; i < H; i += THREADS)
        atomicAdd(&out[i], s_ctx[i]);
}

extern "C" void kernel_launch(void* const* d_in, const int* in_sizes, int n_in,
                              void* d_out, int out_size) {
    const float* query = (const float*)d_in[0];   // [1,1024]
    const float* keys  = (const float*)d_in[1];   // [32768,1024]
    float* out = (float*)d_out;                   // [1,1024]

    zero_out_kernel<<<4, 256>>>(out);
    bahdanau_cos_kernel<<<GRID, THREADS>>>(query, keys, out);
}